// round 2
// baseline (speedup 1.0000x reference)
#include <cuda_runtime.h>
#include <cuda_bf16.h>
#include <cstdint>

// ---------------------------------------------------------------------------
// BinarizedLinear: out = BN( sign(x) @ sign(W)^T )   (bias cancels under BN)
// Build constraint: harness emits compute_103 PTX -> NO tcgen05. Use legacy
// mma.sync m16n8k32 s8 (exact: dot of {-1,0,1} over K=4096 fits s32/f32).
// ---------------------------------------------------------------------------

#define B_DIM   8192
#define K_DIM   4096
#define O_DIM   4096

// Scratch (allocation-free rule: __device__ globals)
__device__ __align__(16) int8_t g_bx8[(size_t)B_DIM * K_DIM];  // sign(x)
__device__ __align__(16) int8_t g_bw8[(size_t)O_DIM * K_DIM];  // sign(W)
__device__ __align__(16) float g_sum[O_DIM];
__device__ __align__(16) float g_ss[O_DIM];
__device__ __align__(16) float g_scale[O_DIM];
__device__ __align__(16) float g_shift[O_DIM];

// ------------------------------- helpers ------------------------------------
__device__ __forceinline__ uint32_t smem_u32(const void* p) {
    uint32_t a;
    asm("{ .reg .u64 t; cvta.to.shared.u64 t, %1; cvt.u32.u64 %0, t; }" : "=r"(a) : "l"(p));
    return a;
}
__device__ __forceinline__ void cp_async16(uint32_t s, const void* g) {
    asm volatile("cp.async.cg.shared.global [%0], [%1], 16;" :: "r"(s), "l"(g));
}
#define CP_COMMIT() asm volatile("cp.async.commit_group;")

__device__ __forceinline__ void ldsm_x4(uint32_t& r0, uint32_t& r1, uint32_t& r2, uint32_t& r3,
                                        uint32_t addr) {
    asm volatile("ldmatrix.sync.aligned.m8n8.x4.shared.b16 {%0,%1,%2,%3}, [%4];"
                 : "=r"(r0), "=r"(r1), "=r"(r2), "=r"(r3) : "r"(addr));
}
__device__ __forceinline__ void mma_s8(int& c0, int& c1, int& c2, int& c3,
                                       uint32_t a0, uint32_t a1, uint32_t a2, uint32_t a3,
                                       uint32_t b0, uint32_t b1) {
    asm volatile("mma.sync.aligned.m16n8k32.row.col.s32.s8.s8.s32 "
                 "{%0,%1,%2,%3}, {%4,%5,%6,%7}, {%8,%9}, {%0,%1,%2,%3};"
                 : "+r"(c0), "+r"(c1), "+r"(c2), "+r"(c3)
                 : "r"(a0), "r"(a1), "r"(a2), "r"(a3), "r"(b0), "r"(b1));
}

// ------------------------------- binarize -----------------------------------
__device__ __forceinline__ uint32_t pack4(float4 v) {
    uint32_t w = 0;
    float f[4] = {v.x, v.y, v.z, v.w};
#pragma unroll
    for (int j = 0; j < 4; j++) {
        int s = (f[j] > 0.0f) ? 1 : ((f[j] < 0.0f) ? -1 : 0);
        w |= (uint32_t)(uint8_t)(int8_t)s << (8 * j);
    }
    return w;
}
__global__ void binarize_kernel(const float* __restrict__ in, int n16, int which) {
    int8_t* dst = which ? g_bw8 : g_bx8;
    int i = blockIdx.x * blockDim.x + threadIdx.x;
    if (i >= n16) return;
    const float4* p = reinterpret_cast<const float4*>(in) + (size_t)i * 4;
    uint4 o;
    o.x = pack4(p[0]); o.y = pack4(p[1]); o.z = pack4(p[2]); o.w = pack4(p[3]);
    reinterpret_cast<uint4*>(dst)[i] = o;
}

// --------------------------------- GEMM -------------------------------------
// CTA 128(M) x 128(N), KC = 64 bytes. 8 warps, warp tile 64x32 (2x4 warp grid).
// SMEM: A/B tiles 128 rows x 64 B each, swizzle: chunk' = chunk ^ ((row>>1)&3)
// (bijective over the 128B bank window for each 8-row ldmatrix phase).
static constexpr int KC = 64;
static constexpr int NKC = K_DIM / KC;              // 64
static constexpr int TILE_B = 128 * 64;             // 8 KB
static constexpr int SMEM_BYTES = 4 * TILE_B + 128; // 2 bufs x (A+B)

__device__ __forceinline__ uint32_t swz(int row, int cb) {  // cb: 16B chunk 0..3
    return (uint32_t)(row * 64 + ((cb ^ ((row >> 1) & 3)) << 4));
}

__device__ __forceinline__ void load_buf(uint32_t sbase, const int8_t* __restrict__ A,
                                         const int8_t* __restrict__ Bm,
                                         int m0, int n0, int kc, int tid) {
    const int8_t* ga = A + (size_t)m0 * K_DIM + kc * KC;
    const int8_t* gb = Bm + (size_t)n0 * K_DIM + kc * KC;
#pragma unroll
    for (int i = 0; i < 2; i++) {                    // 512 chunks / 256 threads
        int c = tid + i * 256;
        int row = c >> 2, cb = c & 3;
        cp_async16(sbase + swz(row, cb), ga + (size_t)row * K_DIM + cb * 16);
        cp_async16(sbase + TILE_B + swz(row, cb), gb + (size_t)row * K_DIM + cb * 16);
    }
}

__global__ void __launch_bounds__(256, 2) gemm_kernel(float* __restrict__ out) {
    extern __shared__ char smem[];
    uint32_t sb = smem_u32(smem);

    const int tid = threadIdx.x, lane = tid & 31, wid = tid >> 5;
    const int m0 = blockIdx.y * 128, n0 = blockIdx.x * 128;
    const int wm = (wid & 1) * 64, wn = (wid >> 1) * 32;

    int acc[4][4][4];
#pragma unroll
    for (int a = 0; a < 4; a++)
#pragma unroll
        for (int b = 0; b < 4; b++)
#pragma unroll
            for (int c = 0; c < 4; c++) acc[a][b][c] = 0;

    // ldmatrix per-lane addressing (same pattern for A and B tiles):
    // row = tileRow + (lane & 15), k-chunk-of-16B selected by (lane & 16)
    const int lrow = lane & 15;
    const int lk16 = (lane >> 4) & 1;   // 0 or 1 -> +16 bytes of K

    load_buf(sb, g_bx8, g_bw8, m0, n0, 0, tid);
    CP_COMMIT();

    for (int kc = 0; kc < NKC; kc++) {
        const uint32_t cur = (uint32_t)(kc & 1) * (2 * TILE_B);
        if (kc + 1 < NKC) {
            const uint32_t nxt = (uint32_t)((kc + 1) & 1) * (2 * TILE_B);
            load_buf(sb + nxt, g_bx8, g_bw8, m0, n0, kc + 1, tid);
            CP_COMMIT();
            asm volatile("cp.async.wait_group 1;");
        } else {
            asm volatile("cp.async.wait_group 0;");
        }
        __syncthreads();

        const uint32_t Ab = sb + cur, Bb = sb + cur + TILE_B;
#pragma unroll
        for (int ks = 0; ks < 2; ks++) {
            const int cb = ks * 2 + lk16;            // 16B chunk index 0..3
            uint32_t a[4][4], b[2][4];
#pragma unroll
            for (int mt = 0; mt < 4; mt++) {
                int row = wm + mt * 16 + lrow;
                ldsm_x4(a[mt][0], a[mt][1], a[mt][2], a[mt][3], Ab + swz(row, cb));
            }
#pragma unroll
            for (int bt = 0; bt < 2; bt++) {
                int row = wn + bt * 16 + lrow;
                ldsm_x4(b[bt][0], b[bt][1], b[bt][2], b[bt][3], Bb + swz(row, cb));
            }
#pragma unroll
            for (int mt = 0; mt < 4; mt++)
#pragma unroll
                for (int nt = 0; nt < 4; nt++) {
                    // x4 regs: r0=(cols+0..7,k0..15) r1=(cols+8..15,k0..15)
                    //          r2=(cols+0..7,k16..31) r3=(cols+8..15,k16..31)
                    uint32_t blo = b[nt >> 1][nt & 1];
                    uint32_t bhi = b[nt >> 1][(nt & 1) + 2];
                    mma_s8(acc[mt][nt][0], acc[mt][nt][1], acc[mt][nt][2], acc[mt][nt][3],
                           a[mt][0], a[mt][1], a[mt][2], a[mt][3], blo, bhi);
                }
        }
        __syncthreads();
    }

    // Epilogue: s32 -> f32 (exact), direct STG.64
    const int gq = lane >> 2, tg = lane & 3;
#pragma unroll
    for (int mt = 0; mt < 4; mt++) {
#pragma unroll
        for (int nt = 0; nt < 4; nt++) {
            int col = n0 + wn + nt * 8 + 2 * tg;
            int row0 = m0 + wm + mt * 16 + gq;
            float2 v0 = make_float2((float)acc[mt][nt][0], (float)acc[mt][nt][1]);
            float2 v1 = make_float2((float)acc[mt][nt][2], (float)acc[mt][nt][3]);
            *reinterpret_cast<float2*>(out + (size_t)row0 * O_DIM + col) = v0;
            *reinterpret_cast<float2*>(out + (size_t)(row0 + 8) * O_DIM + col) = v1;
        }
    }
}

// ------------------------------ BatchNorm -----------------------------------
__global__ void bn_zero() {
    int i = blockIdx.x * blockDim.x + threadIdx.x;
    if (i < O_DIM) { g_sum[i] = 0.f; g_ss[i] = 0.f; }
}
__global__ void bn_reduce(const float* __restrict__ d) {
    int col = blockIdx.x * 256 + threadIdx.x;
    const float* p = d + (size_t)blockIdx.y * 256 * O_DIM + col;
    float s = 0.f, ss = 0.f;
#pragma unroll 8
    for (int r = 0; r < 256; r++) {
        float v = p[(size_t)r * O_DIM];
        s += v;
        ss = fmaf(v, v, ss);
    }
    atomicAdd(&g_sum[col], s);
    atomicAdd(&g_ss[col], ss);
}
__global__ void bn_params() {
    int c = blockIdx.x * blockDim.x + threadIdx.x;
    if (c < O_DIM) {
        float mean = g_sum[c] * (1.0f / B_DIM);
        float var = g_ss[c] * (1.0f / B_DIM) - mean * mean;
        float sc = rsqrtf(var + 1e-5f);
        g_scale[c] = sc;
        g_shift[c] = -mean * sc;
    }
}
__global__ void bn_apply(float* __restrict__ d) {
    int i = blockIdx.x * blockDim.x + threadIdx.x;  // over float4s
    float4 v = reinterpret_cast<float4*>(d)[i];
    int c = (i & (O_DIM / 4 - 1)) << 2;
    float4 sc = *reinterpret_cast<const float4*>(g_scale + c);
    float4 sh = *reinterpret_cast<const float4*>(g_shift + c);
    v.x = fmaf(v.x, sc.x, sh.x);
    v.y = fmaf(v.y, sc.y, sh.y);
    v.z = fmaf(v.z, sc.z, sh.z);
    v.w = fmaf(v.w, sc.w, sh.w);
    reinterpret_cast<float4*>(d)[i] = v;
}

// -------------------------------- launch -------------------------------------
extern "C" void kernel_launch(void* const* d_in, const int* in_sizes, int n_in,
                              void* d_out, int out_size) {
    const float* x = (const float*)d_in[0];
    const float* w = (const float*)d_in[1];
    float* out = (float*)d_out;

    binarize_kernel<<<(B_DIM * K_DIM / 16) / 256, 256>>>(x, B_DIM * K_DIM / 16, 0);
    binarize_kernel<<<(O_DIM * K_DIM / 16) / 256, 256>>>(w, O_DIM * K_DIM / 16, 1);
    bn_zero<<<16, 256>>>();

    gemm_kernel<<<dim3(O_DIM / 128, B_DIM / 128), 256, SMEM_BYTES>>>(out);

    bn_reduce<<<dim3(O_DIM / 256, B_DIM / 256), 256>>>(out);
    bn_params<<<16, 256>>>();
    bn_apply<<<(B_DIM * O_DIM / 4) / 256, 256>>>(out);
}